// round 3
// baseline (speedup 1.0000x reference)
#include <cuda_runtime.h>

#define SEQ   2048
#define H     128
#define B     64
#define OUTF  512
#define NB    4                 // batches per recurrence CTA (weights shared!)
#define NREC  16                // 16 CTAs x 4 batches = 64
#define NFC   132               // 4 col-blocks x 33 CTAs; grid = 148 (one wave)
#define THREADS 384

// Scratch: hidden-state history + per-batch progress watermark
__device__ float g_hs[(size_t)B * SEQ * H];
__device__ int   g_wm[B];

__device__ __forceinline__ unsigned long long ffma2(unsigned long long a,
                                                    unsigned long long b,
                                                    unsigned long long c) {
    unsigned long long d;
    asm("fma.rn.f32x2 %0, %1, %2, %3;" : "=l"(d) : "l"(a), "l"(b), "l"(c));
    return d;
}
__device__ __forceinline__ unsigned long long add2(unsigned long long a,
                                                   unsigned long long b) {
    unsigned long long d;
    asm("add.rn.f32x2 %0, %1, %2;" : "=l"(d) : "l"(a), "l"(b));
    return d;
}
__device__ __forceinline__ float hsum2(unsigned long long v) {
    float lo, hi;
    asm("mov.b64 {%0, %1}, %2;" : "=f"(lo), "=f"(hi) : "l"(v));
    return lo + hi;
}
__device__ __forceinline__ unsigned long long pack2(float lo, float hi) {
    unsigned long long v;
    asm("mov.b64 %0, {%1, %2};" : "=l"(v) : "f"(lo), "f"(hi));
    return v;
}
__device__ __forceinline__ float ex2f(float x) {
    float y; asm("ex2.approx.f32 %0, %1;" : "=f"(y) : "f"(x)); return y;
}
__device__ __forceinline__ float rcpf(float x) {
    float y; asm("rcp.approx.f32 %0, %1;" : "=f"(y) : "f"(x)); return y;
}
__device__ __forceinline__ float fast_sigmoid(float x) {
    return rcpf(1.0f + ex2f(-1.4426950408889634f * x));
}
__device__ __forceinline__ float fast_tanh(float x) {
    float e = ex2f(2.8853900817779268f * x);
    return 1.0f - 2.0f * rcpf(e + 1.0f);
}

// 128-wide dot of register row w[64] (f32x2) against smem vector, bias folded in
__device__ __forceinline__ float dot128(const unsigned long long* w,
                                        const float* hvec,
                                        unsigned long long init) {
    const ulonglong2* h2 = (const ulonglong2*)hvec;
    unsigned long long a0 = init, a1 = 0ull, a2 = 0ull, a3 = 0ull;
    #pragma unroll
    for (int k = 0; k < 16; k++) {
        ulonglong2 hv0 = h2[2 * k];
        ulonglong2 hv1 = h2[2 * k + 1];
        a0 = ffma2(w[4 * k    ], hv0.x, a0);
        a1 = ffma2(w[4 * k + 1], hv0.y, a1);
        a2 = ffma2(w[4 * k + 2], hv1.x, a2);
        a3 = ffma2(w[4 * k + 3], hv1.y, a3);
    }
    a0 = add2(a0, a1);
    a2 = add2(a2, a3);
    a0 = add2(a0, a2);
    return hsum2(a0);
}

__global__ void init_wm_kernel() {
    if (threadIdx.x < B) g_wm[threadIdx.x] = 0;
}

__global__ void __launch_bounds__(THREADS, 1) fused_kernel(
    const float* __restrict__ latent,  // (64,128)
    const float* __restrict__ W_hh,    // (384,128)
    const float* __restrict__ b_ih,    // (384,)
    const float* __restrict__ b_hh,    // (384,)
    const float* __restrict__ fc_W,    // (512,128)
    const float* __restrict__ fc_b,    // (512,)
    float* __restrict__ out)           // (64,2048,512)
{
    // Shared pool: recurrence uses h[4][128] | r[4][128] | z[4][128] (6 KB);
    // FC role uses it as a 32x128 staging tile (16 KB).
    __shared__ __align__(16) float pool[32 * H];

    const int tid = threadIdx.x;

    if (blockIdx.x < NREC) {
        // ============== Recurrence: 4 interleaved batch chains per CTA ==============
        const int b0 = blockIdx.x * NB;
        const int g  = tid >> 7;     // 0: n-rows + tail (warps 0-3), 1: r, 2: z
        const int li = tid & 127;

        float* hP = pool;            // h[j][li]  at pool[j*128 + li]
        float* rP = pool + NB * H;   // r gates
        float* zP = pool + 2 * NB * H;

        const int row = (g == 0) ? (2 * H + li) : ((g == 1) ? li : (H + li));

        // W_hh row in registers (128 regs of f32x2)
        unsigned long long w[64];
        const unsigned long long* Wr =
            (const unsigned long long*)(W_hh + (size_t)row * H);
        #pragma unroll
        for (int k = 0; k < 64; k++) w[k] = Wr[k];

        // Fold biases into the accumulator seed
        const float bsum = (g == 0) ? b_hh[row] : (b_ih[row] + b_hh[row]);
        const unsigned long long acc_init = pack2(bsum, 0.0f);
        const float b_in_i = (g == 0) ? b_ih[row] : 0.0f;  // row == 2H+li for g==0

        // producers' gate output base
        float* gout = (g == 1) ? (rP + li) : (zP + li);

        for (int idx = tid; idx < NB * H; idx += THREADS)
            hP[idx] = latent[(size_t)b0 * H + idx];
        __syncthreads();

        // per-iteration gmem store base: g_hs[b0+j][t][li]
        float* hs_base = g_hs + (size_t)b0 * SEQ * H + li;

        float ggs[NB];

        for (int t = 0; t < SEQ; t++) {
            #pragma unroll
            for (int j = 0; j < NB; j++) {
                float rp, zp, hp;
                if (g == 0 && j > 0) {           // prefetch tail(j-1) operands
                    rp = rP[(j - 1) * H + li];
                    zp = zP[(j - 1) * H + li];
                    hp = hP[(j - 1) * H + li];
                }
                float gg = dot128(w, hP + j * H, acc_init);
                if (g != 0) {
                    gout[j * H] = fast_sigmoid(gg);
                } else {
                    ggs[j] = gg;
                    if (j > 0) {                 // tail for batch j-1 (overlapped)
                        float n  = fast_tanh(fmaf(rp, ggs[j - 1], b_in_i));
                        float hn = fmaf(zp, hp - n, n);
                        hP[(j - 1) * H + li] = hn;
                        hs_base[((size_t)(j - 1) * SEQ + t) * H] = hn;
                    }
                }
                __syncthreads();                 // publish gate[j] (and h[j-1])
            }
            if (g == 0) {                        // tail for batch 3
                float rp = rP[3 * H + li];
                float zp = zP[3 * H + li];
                float hp = hP[3 * H + li];
                float n  = fast_tanh(fmaf(rp, ggs[3], b_in_i));
                float hn = fmaf(zp, hp - n, n);
                hP[3 * H + li] = hn;
                hs_base[((size_t)3 * SEQ + t) * H] = hn;
            }
            // Publish watermarks every 32 steps (needs h[3] store -> extra barrier)
            if ((t & 31) == 31) {
                __syncthreads();
                if (tid == 128) {
                    __threadfence();
                    #pragma unroll
                    for (int j = 0; j < NB; j++) atomicExch(&g_wm[b0 + j], t + 1);
                }
            }
        }
    } else {
        // ================= FC role: consume hs tiles as produced =================
        const int fcid = blockIdx.x - NREC;   // 0..131
        const int cb   = fcid / 33;           // fixed 128-col block
        const int sub  = fcid % 33;
        const int col  = cb * H + (tid & 127);
        const int grp  = tid >> 7;            // 3 row-groups over the 32-row tile

        unsigned long long w[64];
        const unsigned long long* Wr =
            (const unsigned long long*)(fc_W + (size_t)col * H);
        #pragma unroll
        for (int k = 0; k < 64; k++) w[k] = Wr[k];
        const float bias = fc_b[col];

        for (int ent = sub; ent < 64 * B; ent += 33) {
            const int tblk = ent >> 6;
            const int bb   = ent & 63;

            if (tid == 0) {
                const int need = (tblk + 1) * 32;
                while (atomicAdd(&g_wm[bb], 0) < need) __nanosleep(256);
            }
            __syncthreads();

            const float4* src =
                (const float4*)(g_hs + ((size_t)bb * SEQ + (size_t)tblk * 32) * H);
            float4* dst = (float4*)pool;
            #pragma unroll
            for (int it = 0; it < 3; it++) {
                int idx = tid + it * THREADS;
                if (idx < 1024) dst[idx] = src[idx];
            }
            __syncthreads();

            for (int r = grp; r < 32; r += 3) {
                const ulonglong2* hrow = (const ulonglong2*)(pool + r * H);
                unsigned long long a0 = 0ull, a1 = 0ull;
                #pragma unroll
                for (int k = 0; k < 32; k++) {
                    ulonglong2 hv = hrow[k];
                    a0 = ffma2(w[2 * k    ], hv.x, a0);
                    a1 = ffma2(w[2 * k + 1], hv.y, a1);
                }
                out[((size_t)bb * SEQ + (size_t)tblk * 32 + r) * OUTF + col] =
                    hsum2(a0) + hsum2(a1) + bias;
            }
            __syncthreads();
        }
    }
}

extern "C" void kernel_launch(void* const* d_in, const int* in_sizes, int n_in,
                              void* d_out, int out_size) {
    const float* latent = (const float*)d_in[0];
    const float* W_hh   = (const float*)d_in[1];
    const float* b_ih   = (const float*)d_in[2];
    const float* b_hh   = (const float*)d_in[3];
    const float* fc_W   = (const float*)d_in[4];
    const float* fc_b   = (const float*)d_in[5];
    float* out = (float*)d_out;

    init_wm_kernel<<<1, 64>>>();
    fused_kernel<<<NREC + NFC, THREADS>>>(latent, W_hh, b_ih, b_hh, fc_W, fc_b, out);
}

// round 4
// speedup vs baseline: 1.5313x; 1.5313x over previous
#include <cuda_runtime.h>

#define SEQ   2048
#define H     128
#define B     64
#define OUTF  512
#define NREC  64
#define NFC   84
#define THREADS 768

// Scratch: hidden-state history + per-batch progress watermark
__device__ float g_hs[(size_t)B * SEQ * H];
__device__ int   g_wm[B];

__device__ __forceinline__ unsigned long long ffma2(unsigned long long a,
                                                    unsigned long long b,
                                                    unsigned long long c) {
    unsigned long long d;
    asm("fma.rn.f32x2 %0, %1, %2, %3;" : "=l"(d) : "l"(a), "l"(b), "l"(c));
    return d;
}
__device__ __forceinline__ unsigned long long add2(unsigned long long a,
                                                   unsigned long long b) {
    unsigned long long d;
    asm("add.rn.f32x2 %0, %1, %2;" : "=l"(d) : "l"(a), "l"(b));
    return d;
}
__device__ __forceinline__ float hsum2(unsigned long long v) {
    float lo, hi;
    asm("mov.b64 {%0, %1}, %2;" : "=f"(lo), "=f"(hi) : "l"(v));
    return lo + hi;
}
__device__ __forceinline__ unsigned long long pack2(float lo, float hi) {
    unsigned long long v;
    asm("mov.b64 %0, {%1, %2};" : "=l"(v) : "f"(lo), "f"(hi));
    return v;
}
__device__ __forceinline__ float ex2f(float x) {
    float y; asm("ex2.approx.f32 %0, %1;" : "=f"(y) : "f"(x)); return y;
}
__device__ __forceinline__ float rcpf(float x) {
    float y; asm("rcp.approx.f32 %0, %1;" : "=f"(y) : "f"(x)); return y;
}
__device__ __forceinline__ float fast_sigmoid(float x) {
    return rcpf(1.0f + ex2f(-1.4426950408889634f * x));
}
__device__ __forceinline__ float fast_tanh(float x) {
    float e = ex2f(2.8853900817779268f * x);
    return 1.0f - 2.0f * rcpf(e + 1.0f);
}

__global__ void init_wm_kernel() {
    if (threadIdx.x < B) g_wm[threadIdx.x] = 0;
}

__global__ void __launch_bounds__(THREADS, 1) fused_kernel(
    const float* __restrict__ latent,  // (64,128)
    const float* __restrict__ W_hh,    // (384,128)
    const float* __restrict__ b_ih,    // (384,)
    const float* __restrict__ b_hh,    // (384,)
    const float* __restrict__ fc_W,    // (512,128)
    const float* __restrict__ fc_b,    // (512,)
    float* __restrict__ out)           // (64,2048,512)
{
    // Recurrence uses first 3*128 floats (h | r | z); FC uses full 32x128 tile.
    __shared__ __align__(16) float pool[32 * H];

    const int tid = threadIdx.x;

    if (blockIdx.x < NREC) {
        // ====== Recurrence: one batch per CTA; 2 threads per gate row (split-K) ======
        const int b    = blockIdx.x;
        const int row  = tid >> 1;       // 0..383
        const int half = tid & 1;        // low/high 64 elements of the dot
        const int grp  = row >> 7;       // 0:r 1:z 2:n
        const int li   = row & 127;

        float* h_sm = pool;
        float* r_sm = pool + H;
        float* z_sm = pool + 2 * H;

        // Half-row of W_hh in registers: 32 u64 = 64 regs (fits the 85-reg cap)
        unsigned long long w[32];
        {
            const unsigned long long* Wr =
                (const unsigned long long*)(W_hh + (size_t)row * H + half * 64);
            #pragma unroll
            for (int k = 0; k < 32; k++) w[k] = Wr[k];
        }

        // biases folded into one lane's accumulator seed
        const float bsum = (grp == 2) ? b_hh[row] : (b_ih[row] + b_hh[row]);
        const unsigned long long acc_init = pack2(half == 0 ? bsum : 0.0f, 0.0f);
        const float b_in_i = b_ih[row];   // valid only where used (grp==2: row=2H+li)

        const bool is_tail = (grp == 2) && (half == 0);
        float* gate_out = (grp == 0) ? (r_sm + li) : (z_sm + li);

        if (tid < H) h_sm[tid] = latent[(size_t)b * H + tid];
        __syncthreads();

        float* hs_base = g_hs + (size_t)b * SEQ * H + li;

        for (int t = 0; t < SEQ; t++) {
            // ---- half-dot: 64 MACs = 32 packed FMAs, 2 accumulator chains ----
            const ulonglong2* h2 = (const ulonglong2*)h_sm + half * 16;
            unsigned long long a0 = acc_init, a1 = 0ull;
            #pragma unroll
            for (int k = 0; k < 8; k++) {
                ulonglong2 hv0 = h2[2 * k];
                ulonglong2 hv1 = h2[2 * k + 1];
                a0 = ffma2(w[4 * k    ], hv0.x, a0);
                a1 = ffma2(w[4 * k + 1], hv0.y, a1);
                a0 = ffma2(w[4 * k + 2], hv1.x, a0);
                a1 = ffma2(w[4 * k + 3], hv1.y, a1);
            }
            float s = hsum2(add2(a0, a1));
            s += __shfl_xor_sync(0xffffffffu, s, 1);   // pair-sum: full dot + biases

            if (grp != 2) {
                if (half == 0) *gate_out = fast_sigmoid(s);
            }
            __syncthreads();                            // publish r,z

            if (is_tail) {
                float r    = r_sm[li];
                float z    = z_sm[li];
                float hold = h_sm[li];
                float n    = fast_tanh(fmaf(r, s, b_in_i));
                float hn   = fmaf(z, hold - n, n);      // (1-z)*n + z*h
                h_sm[li]   = hn;
                hs_base[(size_t)t * H] = hn;
            }
            __syncthreads();                            // publish h_new

            if ((t & 31) == 31 && tid == 512) {         // tid 512 is a tail thread
                __threadfence();
                atomicExch(&g_wm[b], t + 1);
            }
        }
    } else {
        // ================= FC role: consume hs tiles as produced =================
        const int fcid   = blockIdx.x - NREC;   // 0..83
        const int cb     = fcid / 21;           // fixed 128-col block
        const int sub    = fcid % 21;
        const int half   = tid & 1;
        const int col    = cb * H + ((tid >> 1) & 127);
        const int rowgrp = tid >> 8;            // 0..2 row groups over 32-row tile

        unsigned long long w[32];
        {
            const unsigned long long* Wr =
                (const unsigned long long*)(fc_W + (size_t)col * H + half * 64);
            #pragma unroll
            for (int k = 0; k < 32; k++) w[k] = Wr[k];
        }
        const float bias = fc_b[col];

        for (int ent = sub; ent < 64 * B; ent += 21) {
            const int tblk = ent >> 6;
            const int bb   = ent & 63;

            if (tid == 0) {
                const int need = (tblk + 1) * 32;
                while (atomicAdd(&g_wm[bb], 0) < need) __nanosleep(256);
            }
            __syncthreads();

            // Stage 32x128 fp32 hs tile (16 KB)
            const float4* src =
                (const float4*)(g_hs + ((size_t)bb * SEQ + (size_t)tblk * 32) * H);
            float4* dst = (float4*)pool;
            {
                int idx = tid;
                dst[idx] = src[idx];
                idx += THREADS;
                if (idx < 1024) dst[idx] = src[idx];
            }
            __syncthreads();

            for (int r = rowgrp; r < 32; r += 3) {
                const ulonglong2* hrow =
                    (const ulonglong2*)(pool + r * H) + half * 16;
                unsigned long long a0 = 0ull, a1 = 0ull;
                #pragma unroll
                for (int k = 0; k < 8; k++) {
                    ulonglong2 hv0 = hrow[2 * k];
                    ulonglong2 hv1 = hrow[2 * k + 1];
                    a0 = ffma2(w[4 * k    ], hv0.x, a0);
                    a1 = ffma2(w[4 * k + 1], hv0.y, a1);
                    a0 = ffma2(w[4 * k + 2], hv1.x, a0);
                    a1 = ffma2(w[4 * k + 3], hv1.y, a1);
                }
                float s = hsum2(add2(a0, a1));
                s += __shfl_xor_sync(0xffffffffu, s, 1);
                if (half == 0)
                    out[((size_t)bb * SEQ + (size_t)tblk * 32 + r) * OUTF + col] =
                        s + bias;
            }
            __syncthreads();
        }
    }
}

extern "C" void kernel_launch(void* const* d_in, const int* in_sizes, int n_in,
                              void* d_out, int out_size) {
    const float* latent = (const float*)d_in[0];
    const float* W_hh   = (const float*)d_in[1];
    const float* b_ih   = (const float*)d_in[2];
    const float* b_hh   = (const float*)d_in[3];
    const float* fc_W   = (const float*)d_in[4];
    const float* fc_b   = (const float*)d_in[5];
    float* out = (float*)d_out;

    init_wm_kernel<<<1, 64>>>();
    fused_kernel<<<NREC + NFC, THREADS>>>(latent, W_hh, b_ih, b_hh, fc_W, fc_b, out);
}

// round 6
// speedup vs baseline: 4.4846x; 2.9287x over previous
#include <cuda_runtime.h>

#define SEQ   2048
#define H     128
#define B     64
#define OUTF  512
#define NREC  64
#define NFC   84
#define THREADS 256

// Scratch: hidden-state history + per-batch progress watermark
__device__ float g_hs[(size_t)B * SEQ * H];
__device__ int   g_wm[B];

__device__ __forceinline__ unsigned long long ffma2(unsigned long long a,
                                                    unsigned long long b,
                                                    unsigned long long c) {
    unsigned long long d;
    asm("fma.rn.f32x2 %0, %1, %2, %3;" : "=l"(d) : "l"(a), "l"(b), "l"(c));
    return d;
}
__device__ __forceinline__ unsigned long long add2(unsigned long long a,
                                                   unsigned long long b) {
    unsigned long long d;
    asm("add.rn.f32x2 %0, %1, %2;" : "=l"(d) : "l"(a), "l"(b));
    return d;
}
__device__ __forceinline__ float hsum2(unsigned long long v) {
    float lo, hi;
    asm("mov.b64 {%0, %1}, %2;" : "=f"(lo), "=f"(hi) : "l"(v));
    return lo + hi;
}
__device__ __forceinline__ unsigned long long pack2(float lo, float hi) {
    unsigned long long v;
    asm("mov.b64 %0, {%1, %2};" : "=l"(v) : "f"(lo), "f"(hi));
    return v;
}
__device__ __forceinline__ float ex2f(float x) {
    float y; asm("ex2.approx.f32 %0, %1;" : "=f"(y) : "f"(x)); return y;
}
__device__ __forceinline__ float rcpf(float x) {
    float y; asm("rcp.approx.f32 %0, %1;" : "=f"(y) : "f"(x)); return y;
}
__device__ __forceinline__ float fast_sigmoid(float x) {
    return rcpf(1.0f + ex2f(-1.4426950408889634f * x));
}
__device__ __forceinline__ float fast_tanh(float x) {
    float e = ex2f(2.8853900817779268f * x);
    return 1.0f - 2.0f * rcpf(e + 1.0f);
}

__global__ void init_wm_kernel() {
    if (threadIdx.x < B) g_wm[threadIdx.x] = 0;
}

// Recurrence smem layout: parity p at pool + p*264:
//   copy A (read by half 0) at +0,  copy B (read by half 1) at +132
// 132-float shift => half0's broadcast line and half1's broadcast line
// land in different banks. FC role reuses pool as a 32x128 tile.
#define PAR_STRIDE 264

__global__ void __launch_bounds__(THREADS, 1) fused_kernel(
    const float* __restrict__ latent,  // (64,128)
    const float* __restrict__ W_hh,    // (384,128)
    const float* __restrict__ b_ih,    // (384,)
    const float* __restrict__ b_hh,    // (384,)
    const float* __restrict__ fc_W,    // (512,128)
    const float* __restrict__ fc_b,    // (512,)
    float* __restrict__ out)           // (64,2048,512)
{
    __shared__ __align__(16) float pool[32 * H];

    const int tid = threadIdx.x;

    if (blockIdx.x < NREC) {
        // === Recurrence: one batch/CTA; a lane PAIR owns hidden index li and ===
        // === computes r, z, n dots itself. Ping-pong h, ONE barrier per step. ===
        const int b    = blockIdx.x;
        const int lane = tid & 31;
        const int warp = tid >> 5;            // 0..7
        const int half = lane & 1;            // low/high 64 elems of each dot
        const int li   = warp * 16 + (lane >> 1);   // 0..127

        // Three half-rows of W_hh in registers: 96 u64 = 192 regs
        unsigned long long wr[32], wz[32], wn[32];
        {
            const unsigned long long* W64 = (const unsigned long long*)W_hh;
            const size_t o  = (size_t)half * 32;
            const size_t rr = (size_t)li * 64;
            const size_t rz = (size_t)(H + li) * 64;
            const size_t rn = (size_t)(2 * H + li) * 64;
            #pragma unroll
            for (int k = 0; k < 32; k++) wr[k] = W64[rr + o + k];
            #pragma unroll
            for (int k = 0; k < 32; k++) wz[k] = W64[rz + o + k];
            #pragma unroll
            for (int k = 0; k < 32; k++) wn[k] = W64[rn + o + k];
        }

        // Bias seeds (half 0 carries them)
        const unsigned long long seed_r =
            pack2(half ? 0.0f : (b_ih[li] + b_hh[li]), 0.0f);
        const unsigned long long seed_z =
            pack2(half ? 0.0f : (b_ih[H + li] + b_hh[H + li]), 0.0f);
        const unsigned long long seed_n =
            pack2(half ? 0.0f : b_hh[2 * H + li], 0.0f);
        const float b_in_i = b_ih[2 * H + li];

        // h[li] lives in a register across steps (owned by this lane pair)
        float hold = latent[(size_t)b * H + li];
        // init parity-0 buffers: half0 -> copy A, half1 -> copy B
        pool[half * 132 + li] = hold;
        __syncthreads();

        // write target index within a parity region
        const int widx = half * 132 + li;
        // read offset within a parity region: half0 reads A[0..64),
        // half1 reads B[64..128) => floats 132+64 = 196
        const int roff = half ? 196 : 0;

        float* hs_base = g_hs + (size_t)b * SEQ * H + li;

        for (int t = 0; t < SEQ; t++) {
            const float* rbase = pool + (t & 1) * PAR_STRIDE + roff;
            float*       wbase = pool + ((t + 1) & 1) * PAR_STRIDE;

            const ulonglong2* h2 = (const ulonglong2*)rbase;
            unsigned long long ar0 = seed_r, ar1 = 0ull;
            unsigned long long az0 = seed_z, az1 = 0ull;
            unsigned long long an0 = seed_n, an1 = 0ull;
            #pragma unroll
            for (int k = 0; k < 16; k++) {
                ulonglong2 hv = h2[k];
                ar0 = ffma2(wr[2 * k    ], hv.x, ar0);
                ar1 = ffma2(wr[2 * k + 1], hv.y, ar1);
                az0 = ffma2(wz[2 * k    ], hv.x, az0);
                az1 = ffma2(wz[2 * k + 1], hv.y, az1);
                an0 = ffma2(wn[2 * k    ], hv.x, an0);
                an1 = ffma2(wn[2 * k + 1], hv.y, an1);
            }
            float sr = hsum2(add2(ar0, ar1));
            float sz = hsum2(add2(az0, az1));
            float sn = hsum2(add2(an0, an1));
            sr += __shfl_xor_sync(0xffffffffu, sr, 1);
            sz += __shfl_xor_sync(0xffffffffu, sz, 1);
            sn += __shfl_xor_sync(0xffffffffu, sn, 1);

            float r  = fast_sigmoid(sr);
            float z  = fast_sigmoid(sz);
            float n  = fast_tanh(fmaf(r, sn, b_in_i));
            float hn = fmaf(z, hold - n, n);     // (1-z)*n + z*h
            hold = hn;

            wbase[widx] = hn;                    // ping-pong write (no WAR race)
            if (half == 0) hs_base[(size_t)t * H] = hn;
            __syncthreads();                     // single barrier per step

            if ((t & 31) == 31 && tid == 0) {
                __threadfence();
                atomicExch(&g_wm[b], t + 1);
            }
        }
    } else {
        // ================= FC role: consume hs tiles as produced =================
        const int fcid = blockIdx.x - NREC;   // 0..83
        const int cb   = fcid / 21;           // fixed 128-col block
        const int sub  = fcid % 21;
        const int col  = cb * H + (tid & 127);
        const int grp  = tid >> 7;            // 2 row-groups over the 32-row tile

        unsigned long long w[64];
        {
            const unsigned long long* Wr =
                (const unsigned long long*)(fc_W + (size_t)col * H);
            #pragma unroll
            for (int k = 0; k < 64; k++) w[k] = Wr[k];
        }
        const float bias = fc_b[col];

        for (int ent = sub; ent < 64 * B; ent += 21) {
            const int tblk = ent >> 6;
            const int bb   = ent & 63;

            if (tid == 0) {
                const int need = (tblk + 1) * 32;
                while (atomicAdd(&g_wm[bb], 0) < need) __nanosleep(256);
            }
            __syncthreads();

            // Stage 32x128 fp32 hs tile (16 KB)
            const float4* src =
                (const float4*)(g_hs + ((size_t)bb * SEQ + (size_t)tblk * 32) * H);
            float4* dst = (float4*)pool;
            #pragma unroll
            for (int it = 0; it < 4; it++) {
                int idx = tid + it * THREADS;
                dst[idx] = src[idx];
            }
            __syncthreads();

            for (int r = grp; r < 32; r += 2) {
                const ulonglong2* hrow = (const ulonglong2*)(pool + r * H);
                unsigned long long a0 = 0ull, a1 = 0ull;
                #pragma unroll
                for (int k = 0; k < 32; k++) {
                    ulonglong2 hv = hrow[k];
                    a0 = ffma2(w[2 * k    ], hv.x, a0);
                    a1 = ffma2(w[2 * k + 1], hv.y, a1);
                }
                out[((size_t)bb * SEQ + (size_t)tblk * 32 + r) * OUTF + col] =
                    hsum2(add2(a0, a1)) + bias;
            }
            __syncthreads();
        }
    }
}

extern "C" void kernel_launch(void* const* d_in, const int* in_sizes, int n_in,
                              void* d_out, int out_size) {
    const float* latent = (const float*)d_in[0];
    const float* W_hh   = (const float*)d_in[1];
    const float* b_ih   = (const float*)d_in[2];
    const float* b_hh   = (const float*)d_in[3];
    const float* fc_W   = (const float*)d_in[4];
    const float* fc_b   = (const float*)d_in[5];
    float* out = (float*)d_out;

    init_wm_kernel<<<1, 64>>>();
    fused_kernel<<<NREC + NFC, THREADS>>>(latent, W_hh, b_ih, b_hh, fc_W, fc_b, out);
}

// round 7
// speedup vs baseline: 4.5770x; 1.0206x over previous
#include <cuda_runtime.h>

#define SEQ   2048
#define H     128
#define B     64
#define OUTF  512
#define NREC  64
#define NFC   84
#define THREADS 256

// Scratch: hidden-state history + per-batch progress watermark
__device__ float g_hs[(size_t)B * SEQ * H];
__device__ int   g_wm[B];

__device__ __forceinline__ unsigned long long ffma2(unsigned long long a,
                                                    unsigned long long b,
                                                    unsigned long long c) {
    unsigned long long d;
    asm("fma.rn.f32x2 %0, %1, %2, %3;" : "=l"(d) : "l"(a), "l"(b), "l"(c));
    return d;
}
__device__ __forceinline__ unsigned long long add2(unsigned long long a,
                                                   unsigned long long b) {
    unsigned long long d;
    asm("add.rn.f32x2 %0, %1, %2;" : "=l"(d) : "l"(a), "l"(b));
    return d;
}
__device__ __forceinline__ float hsum2(unsigned long long v) {
    float lo, hi;
    asm("mov.b64 {%0, %1}, %2;" : "=f"(lo), "=f"(hi) : "l"(v));
    return lo + hi;
}
__device__ __forceinline__ float ex2f(float x) {
    float y; asm("ex2.approx.f32 %0, %1;" : "=f"(y) : "f"(x)); return y;
}
__device__ __forceinline__ float rcpf(float x) {
    float y; asm("rcp.approx.f32 %0, %1;" : "=f"(y) : "f"(x)); return y;
}
__device__ __forceinline__ float fast_sigmoid(float x) {
    return rcpf(1.0f + ex2f(-1.4426950408889634f * x));
}
__device__ __forceinline__ float fast_tanh(float x) {
    float e = ex2f(2.8853900817779268f * x);
    return 1.0f - 2.0f * rcpf(e + 1.0f);
}

__global__ void init_wm_kernel() {
    if (threadIdx.x < B) g_wm[threadIdx.x] = 0;
}

// Recurrence smem layout: parity p at pool + p*264:
//   copy A (read by half 0) at +0,  copy B (read by half 1) at +132
// 132-float shift => the two broadcast lines land in different banks.
#define PAR_STRIDE 264

struct StepOut { float hn; };

__global__ void __launch_bounds__(THREADS, 1) fused_kernel(
    const float* __restrict__ latent,  // (64,128)
    const float* __restrict__ W_hh,    // (384,128)
    const float* __restrict__ b_ih,    // (384,)
    const float* __restrict__ b_hh,    // (384,)
    const float* __restrict__ fc_W,    // (512,128)
    const float* __restrict__ fc_b,    // (512,)
    float* __restrict__ out)           // (64,2048,512)
{
    __shared__ __align__(16) float pool[32 * H];

    const int tid = threadIdx.x;

    if (blockIdx.x < NREC) {
        // === Recurrence: one batch/CTA; a lane PAIR owns hidden index li and ===
        // === computes r, z, n dots itself. Ping-pong h, ONE barrier per step. ===
        const int b    = blockIdx.x;
        const int lane = tid & 31;
        const int warp = tid >> 5;            // 0..7
        const int half = lane & 1;            // low/high 64 elems of each dot
        const int li   = warp * 16 + (lane >> 1);   // 0..127

        // Three half-rows of W_hh in registers: 96 u64 = 192 regs
        unsigned long long wr[32], wz[32], wn[32];
        {
            const unsigned long long* W64 = (const unsigned long long*)W_hh;
            const size_t o  = (size_t)half * 32;
            const size_t rr = (size_t)li * 64;
            const size_t rz = (size_t)(H + li) * 64;
            const size_t rn = (size_t)(2 * H + li) * 64;
            #pragma unroll
            for (int k = 0; k < 32; k++) wr[k] = W64[rr + o + k];
            #pragma unroll
            for (int k = 0; k < 32; k++) wz[k] = W64[rz + o + k];
            #pragma unroll
            for (int k = 0; k < 32; k++) wn[k] = W64[rn + o + k];
        }

        // Scalar biases, added after the pair reduction (no u64 seeds)
        const float bs_r   = b_ih[li] + b_hh[li];
        const float bs_z   = b_ih[H + li] + b_hh[H + li];
        const float bs_n   = b_hh[2 * H + li];
        const float b_in_i = b_ih[2 * H + li];

        // h[li] lives in a register across steps (owned by this lane pair)
        float hold = latent[(size_t)b * H + li];
        pool[half * 132 + li] = hold;          // init parity-0 buffers
        __syncthreads();

        const int widx = half * 132 + li;      // write index within a parity region
        const int roff = half ? 196 : 0;       // read offset within a parity region

        const float* rb0 = pool + roff;              // parity 0 read base
        const float* rb1 = pool + PAR_STRIDE + roff; // parity 1 read base
        float*       wb0 = pool;                     // parity 0 write base
        float*       wb1 = pool + PAR_STRIDE;

        float* hs_base = g_hs + (size_t)b * SEQ * H + li;

        // one GRU step: read h from rbase, write new h to wbase
        auto step = [&](const float* rbase, float* wbase, int t) {
            const ulonglong2* h2 = (const ulonglong2*)rbase;
            unsigned long long ar = 0ull, az = 0ull, an = 0ull;
            #pragma unroll
            for (int k = 0; k < 16; k++) {
                ulonglong2 hv = h2[k];
                ar = ffma2(wr[2 * k], hv.x, ar);
                az = ffma2(wz[2 * k], hv.x, az);
                an = ffma2(wn[2 * k], hv.x, an);
                ar = ffma2(wr[2 * k + 1], hv.y, ar);
                az = ffma2(wz[2 * k + 1], hv.y, az);
                an = ffma2(wn[2 * k + 1], hv.y, an);
            }
            float sr = hsum2(ar);
            float sz = hsum2(az);
            float sn = hsum2(an);
            sr += __shfl_xor_sync(0xffffffffu, sr, 1);
            sz += __shfl_xor_sync(0xffffffffu, sz, 1);
            sn += __shfl_xor_sync(0xffffffffu, sn, 1);

            float r  = fast_sigmoid(sr + bs_r);
            float z  = fast_sigmoid(sz + bs_z);
            float n  = fast_tanh(fmaf(r, sn + bs_n, b_in_i));
            float hn = fmaf(z, hold - n, n);     // (1-z)*n + z*h
            hold = hn;

            wbase[widx] = hn;                    // ping-pong write (no WAR race)
            if (half == 0) hs_base[(size_t)t * H] = hn;
            __syncthreads();                     // single barrier per step
        };

        for (int to = 0; to < SEQ; to += 32) {
            #pragma unroll 1
            for (int ti = 0; ti < 32; ti += 2) {
                step(rb0, wb1, to + ti);         // even step: parity 0 -> 1
                step(rb1, wb0, to + ti + 1);     // odd  step: parity 1 -> 0
            }
            if (tid == 0) {
                __threadfence();
                atomicExch(&g_wm[b], to + 32);
            }
        }
    } else {
        // ================= FC role: consume hs tiles as produced =================
        const int fcid = blockIdx.x - NREC;   // 0..83
        const int cb   = fcid / 21;           // fixed 128-col block
        const int sub  = fcid % 21;
        const int col  = cb * H + (tid & 127);
        const int grp  = tid >> 7;            // 2 row-groups over the 32-row tile

        unsigned long long w[64];
        {
            const unsigned long long* Wr =
                (const unsigned long long*)(fc_W + (size_t)col * H);
            #pragma unroll
            for (int k = 0; k < 64; k++) w[k] = Wr[k];
        }
        const float bias = fc_b[col];

        for (int ent = sub; ent < 64 * B; ent += 21) {
            const int tblk = ent >> 6;
            const int bb   = ent & 63;

            if (tid == 0) {
                const int need = (tblk + 1) * 32;
                while (atomicAdd(&g_wm[bb], 0) < need) __nanosleep(256);
            }
            __syncthreads();

            // Stage 32x128 fp32 hs tile (16 KB)
            const float4* src =
                (const float4*)(g_hs + ((size_t)bb * SEQ + (size_t)tblk * 32) * H);
            float4* dst = (float4*)pool;
            #pragma unroll
            for (int it = 0; it < 4; it++) {
                int idx = tid + it * THREADS;
                dst[idx] = src[idx];
            }
            __syncthreads();

            for (int r = grp; r < 32; r += 2) {
                const ulonglong2* hrow = (const ulonglong2*)(pool + r * H);
                unsigned long long a0 = 0ull, a1 = 0ull;
                #pragma unroll
                for (int k = 0; k < 32; k++) {
                    ulonglong2 hv = hrow[k];
                    a0 = ffma2(w[2 * k    ], hv.x, a0);
                    a1 = ffma2(w[2 * k + 1], hv.y, a1);
                }
                out[((size_t)bb * SEQ + (size_t)tblk * 32 + r) * OUTF + col] =
                    hsum2(add2(a0, a1)) + bias;
            }
            __syncthreads();
        }
    }
}

extern "C" void kernel_launch(void* const* d_in, const int* in_sizes, int n_in,
                              void* d_out, int out_size) {
    const float* latent = (const float*)d_in[0];
    const float* W_hh   = (const float*)d_in[1];
    const float* b_ih   = (const float*)d_in[2];
    const float* b_hh   = (const float*)d_in[3];
    const float* fc_W   = (const float*)d_in[4];
    const float* fc_b   = (const float*)d_in[5];
    float* out = (float*)d_out;

    init_wm_kernel<<<1, 64>>>();
    fused_kernel<<<NREC + NFC, THREADS>>>(latent, W_hh, b_ih, b_hh, fc_W, fc_b, out);
}